// round 10
// baseline (speedup 1.0000x reference)
#include <cuda_runtime.h>

// 2-level 2D Haar DWT, fully fused. (Round-1 kernel — best measured config:
// kernel 26.1us, DRAM 71.3%, occ 75%. Cache hints / bigger tiles / software
// pipelining all measured neutral-or-worse; this problem sits at the HBM
// mixed read/write stream ceiling.)
//
// x: [96, 512, 512] (B*C flattened), fp32.
// out layout (tuple order, each flattened):
//   a2,h2,v2,d2 : [96,128,128]  (L2 = 1,572,864 elems each)
//   h1,v1,d1    : [96,256,256]  (4*L2 elems each)
// Each thread handles one 4x4 input block -> 4 of each h1/v1/d1 + 1 of each L2 output.

#define L2ELEMS (96u * 128u * 128u)   // 1,572,864

__global__ void __launch_bounds__(256) haar2_kernel(const float* __restrict__ x,
                                                    float* __restrict__ out)
{
    unsigned tid = blockIdx.x * blockDim.x + threadIdx.x;   // 0 .. 96*128*128-1
    unsigned w  = tid & 127u;           // block col (of 4-wide blocks)
    unsigned h  = (tid >> 7) & 127u;    // block row
    unsigned bc = tid >> 14;            // batch*channel, 0..95

    const float* xp = x + ((size_t)bc * 512u + 4u * h) * 512u + 4u * w;
    float4 r0 = *(const float4*)(xp);
    float4 r1 = *(const float4*)(xp + 512);
    float4 r2 = *(const float4*)(xp + 1024);
    float4 r3 = *(const float4*)(xp + 1536);

    // Level-1 butterflies over four 2x2 sub-blocks.
    float aa00, aa01, aa10, aa11;
    float h1v[4], v1v[4], d1v[4];   // index = sr*2+sc

    {   // sr=0, sc=0
        float sTop = r0.x + r0.y, sBot = r1.x + r1.y;
        float dTop = r0.x - r0.y, dBot = r1.x - r1.y;
        aa00   = 0.5f * (sTop + sBot);
        h1v[0] = 0.5f * (sTop - sBot);
        v1v[0] = 0.5f * (dTop + dBot);
        d1v[0] = 0.5f * (dTop - dBot);
    }
    {   // sr=0, sc=1
        float sTop = r0.z + r0.w, sBot = r1.z + r1.w;
        float dTop = r0.z - r0.w, dBot = r1.z - r1.w;
        aa01   = 0.5f * (sTop + sBot);
        h1v[1] = 0.5f * (sTop - sBot);
        v1v[1] = 0.5f * (dTop + dBot);
        d1v[1] = 0.5f * (dTop - dBot);
    }
    {   // sr=1, sc=0
        float sTop = r2.x + r2.y, sBot = r3.x + r3.y;
        float dTop = r2.x - r2.y, dBot = r3.x - r3.y;
        aa10   = 0.5f * (sTop + sBot);
        h1v[2] = 0.5f * (sTop - sBot);
        v1v[2] = 0.5f * (dTop + dBot);
        d1v[2] = 0.5f * (dTop - dBot);
    }
    {   // sr=1, sc=1
        float sTop = r2.z + r2.w, sBot = r3.z + r3.w;
        float dTop = r2.z - r2.w, dBot = r3.z - r3.w;
        aa11   = 0.5f * (sTop + sBot);
        h1v[3] = 0.5f * (sTop - sBot);
        v1v[3] = 0.5f * (dTop + dBot);
        d1v[3] = 0.5f * (dTop - dBot);
    }

    // Level-2 butterfly on aa's.
    float sTop = aa00 + aa01, sBot = aa10 + aa11;
    float dTop = aa00 - aa01, dBot = aa10 - aa11;
    float a2v  = 0.5f * (sTop + sBot);
    float h2v  = 0.5f * (sTop - sBot);
    float v2v  = 0.5f * (dTop + dBot);
    float d2v  = 0.5f * (dTop - dBot);

    // ---- stores ----
    float* a2o = out;
    float* h2o = out + (size_t)L2ELEMS;
    float* v2o = out + (size_t)2 * L2ELEMS;
    float* d2o = out + (size_t)3 * L2ELEMS;
    float* h1o = out + (size_t)4 * L2ELEMS;
    float* v1o = out + (size_t)8 * L2ELEMS;
    float* d1o = out + (size_t)12 * L2ELEMS;

    // level-1 outputs: [96,256,256], position (2h+sr, 2w+sc); float2 per row
    size_t base1 = (size_t)bc * 65536u + (size_t)(2u * h) * 256u + 2u * w;
    *(float2*)(h1o + base1)        = make_float2(h1v[0], h1v[1]);
    *(float2*)(h1o + base1 + 256)  = make_float2(h1v[2], h1v[3]);
    *(float2*)(v1o + base1)        = make_float2(v1v[0], v1v[1]);
    *(float2*)(v1o + base1 + 256)  = make_float2(v1v[2], v1v[3]);
    *(float2*)(d1o + base1)        = make_float2(d1v[0], d1v[1]);
    *(float2*)(d1o + base1 + 256)  = make_float2(d1v[2], d1v[3]);

    // level-2 outputs: [96,128,128]
    size_t base2 = (size_t)bc * 16384u + (size_t)h * 128u + w;
    a2o[base2] = a2v;
    h2o[base2] = h2v;
    v2o[base2] = v2v;
    d2o[base2] = d2v;
}

extern "C" void kernel_launch(void* const* d_in, const int* in_sizes, int n_in,
                              void* d_out, int out_size)
{
    const float* x = (const float*)d_in[0];
    float* out = (float*)d_out;
    // 96 * 128 * 128 threads, one per 4x4 block
    unsigned total = 96u * 128u * 128u;
    haar2_kernel<<<total / 256u, 256u>>>(x, out);
}

// round 12
// speedup vs baseline: 1.0063x; 1.0063x over previous
#include <cuda_runtime.h>

// 2-level 2D Haar DWT, fully fused. FINAL — converged config.
// Measured: kernel ~26.1-26.5us, DRAM ~70% busy @ ~5.5TB/s, occ ~77%.
// The problem is bound by the HBM mixed read/write stream ceiling; structural
// variants (bigger tiles, software pipelining) and L2 cache-policy hints
// (.cs, evict_last) were all measured neutral-or-worse across rounds 3-9.
//
// x: [96, 512, 512] (B*C flattened), fp32.
// out layout (tuple order, each flattened):
//   a2,h2,v2,d2 : [96,128,128]  (L2 = 1,572,864 elems each)
//   h1,v1,d1    : [96,256,256]  (4*L2 elems each)
// Each thread handles one 4x4 input block -> 4 of each h1/v1/d1 + 1 of each L2 output.

#define L2ELEMS (96u * 128u * 128u)   // 1,572,864

__global__ void __launch_bounds__(256) haar2_kernel(const float* __restrict__ x,
                                                    float* __restrict__ out)
{
    unsigned tid = blockIdx.x * blockDim.x + threadIdx.x;   // 0 .. 96*128*128-1
    unsigned w  = tid & 127u;           // block col (of 4-wide blocks)
    unsigned h  = (tid >> 7) & 127u;    // block row
    unsigned bc = tid >> 14;            // batch*channel, 0..95

    const float* xp = x + ((size_t)bc * 512u + 4u * h) * 512u + 4u * w;
    float4 r0 = *(const float4*)(xp);
    float4 r1 = *(const float4*)(xp + 512);
    float4 r2 = *(const float4*)(xp + 1024);
    float4 r3 = *(const float4*)(xp + 1536);

    // Level-1 butterflies over four 2x2 sub-blocks.
    float aa00, aa01, aa10, aa11;
    float h1v[4], v1v[4], d1v[4];   // index = sr*2+sc

    {   // sr=0, sc=0
        float sTop = r0.x + r0.y, sBot = r1.x + r1.y;
        float dTop = r0.x - r0.y, dBot = r1.x - r1.y;
        aa00   = 0.5f * (sTop + sBot);
        h1v[0] = 0.5f * (sTop - sBot);
        v1v[0] = 0.5f * (dTop + dBot);
        d1v[0] = 0.5f * (dTop - dBot);
    }
    {   // sr=0, sc=1
        float sTop = r0.z + r0.w, sBot = r1.z + r1.w;
        float dTop = r0.z - r0.w, dBot = r1.z - r1.w;
        aa01   = 0.5f * (sTop + sBot);
        h1v[1] = 0.5f * (sTop - sBot);
        v1v[1] = 0.5f * (dTop + dBot);
        d1v[1] = 0.5f * (dTop - dBot);
    }
    {   // sr=1, sc=0
        float sTop = r2.x + r2.y, sBot = r3.x + r3.y;
        float dTop = r2.x - r2.y, dBot = r3.x - r3.y;
        aa10   = 0.5f * (sTop + sBot);
        h1v[2] = 0.5f * (sTop - sBot);
        v1v[2] = 0.5f * (dTop + dBot);
        d1v[2] = 0.5f * (dTop - dBot);
    }
    {   // sr=1, sc=1
        float sTop = r2.z + r2.w, sBot = r3.z + r3.w;
        float dTop = r2.z - r2.w, dBot = r3.z - r3.w;
        aa11   = 0.5f * (sTop + sBot);
        h1v[3] = 0.5f * (sTop - sBot);
        v1v[3] = 0.5f * (dTop + dBot);
        d1v[3] = 0.5f * (dTop - dBot);
    }

    // Level-2 butterfly on aa's.
    float sTop = aa00 + aa01, sBot = aa10 + aa11;
    float dTop = aa00 - aa01, dBot = aa10 - aa11;
    float a2v  = 0.5f * (sTop + sBot);
    float h2v  = 0.5f * (sTop - sBot);
    float v2v  = 0.5f * (dTop + dBot);
    float d2v  = 0.5f * (dTop - dBot);

    // ---- stores ----
    float* a2o = out;
    float* h2o = out + (size_t)L2ELEMS;
    float* v2o = out + (size_t)2 * L2ELEMS;
    float* d2o = out + (size_t)3 * L2ELEMS;
    float* h1o = out + (size_t)4 * L2ELEMS;
    float* v1o = out + (size_t)8 * L2ELEMS;
    float* d1o = out + (size_t)12 * L2ELEMS;

    // level-1 outputs: [96,256,256], position (2h+sr, 2w+sc); float2 per row
    size_t base1 = (size_t)bc * 65536u + (size_t)(2u * h) * 256u + 2u * w;
    *(float2*)(h1o + base1)        = make_float2(h1v[0], h1v[1]);
    *(float2*)(h1o + base1 + 256)  = make_float2(h1v[2], h1v[3]);
    *(float2*)(v1o + base1)        = make_float2(v1v[0], v1v[1]);
    *(float2*)(v1o + base1 + 256)  = make_float2(v1v[2], v1v[3]);
    *(float2*)(d1o + base1)        = make_float2(d1v[0], d1v[1]);
    *(float2*)(d1o + base1 + 256)  = make_float2(d1v[2], d1v[3]);

    // level-2 outputs: [96,128,128]
    size_t base2 = (size_t)bc * 16384u + (size_t)h * 128u + w;
    a2o[base2] = a2v;
    h2o[base2] = h2v;
    v2o[base2] = v2v;
    d2o[base2] = d2v;
}

extern "C" void kernel_launch(void* const* d_in, const int* in_sizes, int n_in,
                              void* d_out, int out_size)
{
    const float* x = (const float*)d_in[0];
    float* out = (float*)d_out;
    // 96 * 128 * 128 threads, one per 4x4 block
    unsigned total = 96u * 128u * 128u;
    haar2_kernel<<<total / 256u, 256u>>>(x, out);
}

// round 15
// speedup vs baseline: 1.0073x; 1.0009x over previous
#include <cuda_runtime.h>

// 2-level 2D Haar DWT, fully fused. FINAL — converged config.
// Measured (3 reproductions): kernel 26.1-26.5us, DRAM ~70% @ ~5.5TB/s, occ ~75%.
// Bound by the HBM mixed read/write stream ceiling. Structural variants
// (4x8 tiles, software pipelining) and L2 cache-policy hints (.cs, evict_last)
// all measured neutral-or-worse across rounds 3-9.
//
// x: [96, 512, 512] (B*C flattened), fp32.
// out layout (tuple order, each flattened):
//   a2,h2,v2,d2 : [96,128,128]  (L2 = 1,572,864 elems each)
//   h1,v1,d1    : [96,256,256]  (4*L2 elems each)
// Each thread handles one 4x4 input block -> 4 of each h1/v1/d1 + 1 of each L2 output.

#define L2ELEMS (96u * 128u * 128u)   // 1,572,864

__global__ void __launch_bounds__(256) haar2_kernel(const float* __restrict__ x,
                                                    float* __restrict__ out)
{
    unsigned tid = blockIdx.x * blockDim.x + threadIdx.x;   // 0 .. 96*128*128-1
    unsigned w  = tid & 127u;           // block col (of 4-wide blocks)
    unsigned h  = (tid >> 7) & 127u;    // block row
    unsigned bc = tid >> 14;            // batch*channel, 0..95

    const float* xp = x + ((size_t)bc * 512u + 4u * h) * 512u + 4u * w;
    float4 r0 = *(const float4*)(xp);
    float4 r1 = *(const float4*)(xp + 512);
    float4 r2 = *(const float4*)(xp + 1024);
    float4 r3 = *(const float4*)(xp + 1536);

    // Level-1 butterflies over four 2x2 sub-blocks.
    float aa00, aa01, aa10, aa11;
    float h1v[4], v1v[4], d1v[4];   // index = sr*2+sc

    {   // sr=0, sc=0
        float sTop = r0.x + r0.y, sBot = r1.x + r1.y;
        float dTop = r0.x - r0.y, dBot = r1.x - r1.y;
        aa00   = 0.5f * (sTop + sBot);
        h1v[0] = 0.5f * (sTop - sBot);
        v1v[0] = 0.5f * (dTop + dBot);
        d1v[0] = 0.5f * (dTop - dBot);
    }
    {   // sr=0, sc=1
        float sTop = r0.z + r0.w, sBot = r1.z + r1.w;
        float dTop = r0.z - r0.w, dBot = r1.z - r1.w;
        aa01   = 0.5f * (sTop + sBot);
        h1v[1] = 0.5f * (sTop - sBot);
        v1v[1] = 0.5f * (dTop + dBot);
        d1v[1] = 0.5f * (dTop - dBot);
    }
    {   // sr=1, sc=0
        float sTop = r2.x + r2.y, sBot = r3.x + r3.y;
        float dTop = r2.x - r2.y, dBot = r3.x - r3.y;
        aa10   = 0.5f * (sTop + sBot);
        h1v[2] = 0.5f * (sTop - sBot);
        v1v[2] = 0.5f * (dTop + dBot);
        d1v[2] = 0.5f * (dTop - dBot);
    }
    {   // sr=1, sc=1
        float sTop = r2.z + r2.w, sBot = r3.z + r3.w;
        float dTop = r2.z - r2.w, dBot = r3.z - r3.w;
        aa11   = 0.5f * (sTop + sBot);
        h1v[3] = 0.5f * (sTop - sBot);
        v1v[3] = 0.5f * (dTop + dBot);
        d1v[3] = 0.5f * (dTop - dBot);
    }

    // Level-2 butterfly on aa's.
    float sTop = aa00 + aa01, sBot = aa10 + aa11;
    float dTop = aa00 - aa01, dBot = aa10 - aa11;
    float a2v  = 0.5f * (sTop + sBot);
    float h2v  = 0.5f * (sTop - sBot);
    float v2v  = 0.5f * (dTop + dBot);
    float d2v  = 0.5f * (dTop - dBot);

    // ---- stores ----
    float* a2o = out;
    float* h2o = out + (size_t)L2ELEMS;
    float* v2o = out + (size_t)2 * L2ELEMS;
    float* d2o = out + (size_t)3 * L2ELEMS;
    float* h1o = out + (size_t)4 * L2ELEMS;
    float* v1o = out + (size_t)8 * L2ELEMS;
    float* d1o = out + (size_t)12 * L2ELEMS;

    // level-1 outputs: [96,256,256], position (2h+sr, 2w+sc); float2 per row
    size_t base1 = (size_t)bc * 65536u + (size_t)(2u * h) * 256u + 2u * w;
    *(float2*)(h1o + base1)        = make_float2(h1v[0], h1v[1]);
    *(float2*)(h1o + base1 + 256)  = make_float2(h1v[2], h1v[3]);
    *(float2*)(v1o + base1)        = make_float2(v1v[0], v1v[1]);
    *(float2*)(v1o + base1 + 256)  = make_float2(v1v[2], v1v[3]);
    *(float2*)(d1o + base1)        = make_float2(d1v[0], d1v[1]);
    *(float2*)(d1o + base1 + 256)  = make_float2(d1v[2], d1v[3]);

    // level-2 outputs: [96,128,128]
    size_t base2 = (size_t)bc * 16384u + (size_t)h * 128u + w;
    a2o[base2] = a2v;
    h2o[base2] = h2v;
    v2o[base2] = v2v;
    d2o[base2] = d2v;
}

extern "C" void kernel_launch(void* const* d_in, const int* in_sizes, int n_in,
                              void* d_out, int out_size)
{
    const float* x = (const float*)d_in[0];
    float* out = (float*)d_out;
    // 96 * 128 * 128 threads, one per 4x4 block
    unsigned total = 96u * 128u * 128u;
    haar2_kernel<<<total / 256u, 256u>>>(x, out);
}